// round 16
// baseline (speedup 1.0000x reference)
#include <cuda_runtime.h>
#include <cstdint>
#include <cstddef>

// ---------------------------------------------------------------------------
// GIN (3-layer) — Round 16.
// Base = R15 (233.5us). One change: gather via cp.async double-buffered
// edge batches (bypasses RF; ~4x more bytes in flight -> toward the L2 cap).
// GEMM (R13 form) and CSR frozen.
// ---------------------------------------------------------------------------

#define N_NODES 10000
#define N_EDGES 640000
#define INC     128
#define HIDC    256

__device__ float g_agg[N_NODES * HIDC];
__device__ float g_hid[N_NODES * HIDC];
__device__ float g_f1 [N_NODES * HIDC];
__device__ float g_f2 [N_NODES * HIDC];
__device__ float g_wt [6 * HIDC * HIDC];
__device__ int   g_deg[N_NODES];        // invariant: zero at kernel_launch entry
__device__ int   g_off[N_NODES + 1];
__device__ int   g_rank[N_EDGES];
__device__ int   g_eid[N_EDGES];

// ---------------------------------------------------------------------------
__device__ __forceinline__ uint32_t smem_u32(const void* p) {
    uint32_t a;
    asm("{ .reg .u64 t; cvta.to.shared.u64 t, %1; cvt.u32.u64 %0, t; }" : "=r"(a) : "l"(p));
    return a;
}
__device__ __forceinline__ float tf32r(float v) {
    uint32_t r;
    asm("cvt.rna.tf32.f32 %0, %1;" : "=r"(r) : "f"(v));
    return __uint_as_float(r);
}
__device__ __forceinline__ void cp16(uint32_t saddr, const void* g, int sz) {
    asm volatile("cp.async.cg.shared.global [%0], [%1], 16, %2;"
                 :: "r"(saddr), "l"(g), "r"(sz) : "memory");
}
__device__ __forceinline__ void cp_commit() {
    asm volatile("cp.async.commit_group;" ::: "memory");
}
template <int N>
__device__ __forceinline__ void cp_wait() {
    asm volatile("cp.async.wait_group %0;" :: "n"(N) : "memory");
}
__device__ __forceinline__ void ldsm_x4(uint32_t& r0, uint32_t& r1,
                                        uint32_t& r2, uint32_t& r3,
                                        uint32_t addr) {
    asm volatile("ldmatrix.sync.aligned.m8n8.x4.shared.b16 {%0,%1,%2,%3}, [%4];"
                 : "=r"(r0), "=r"(r1), "=r"(r2), "=r"(r3) : "r"(addr));
}
__device__ __forceinline__ void mma_tf32(float* c, uint32_t a0, uint32_t a1,
                                         uint32_t a2, uint32_t a3,
                                         uint32_t b0, uint32_t b1) {
    asm volatile(
        "mma.sync.aligned.m16n8k8.row.col.f32.tf32.tf32.f32 "
        "{%0,%1,%2,%3}, {%4,%5,%6,%7}, {%8,%9}, {%0,%1,%2,%3};"
        : "+f"(c[0]), "+f"(c[1]), "+f"(c[2]), "+f"(c[3])
        : "r"(a0), "r"(a1), "r"(a2), "r"(a3), "r"(b0), "r"(b1));
}

// ---------------------------------------------------------------------------
// Fused: blocks [0, CNT_BLKS) degree count + per-edge rank; rest: transpose.
// ---------------------------------------------------------------------------
#define CNT_BLKS 625
#define TW_ELEMS (256 * INC + 5 * 256 * HIDC)
#define TW_BLKS  ((TW_ELEMS + 255) / 256)

__global__ void __launch_bounds__(256) count_and_transpose(
    const int* __restrict__ ei,
    const float* __restrict__ W0, const float* __restrict__ W1,
    const float* __restrict__ W2, const float* __restrict__ W3,
    const float* __restrict__ W4, const float* __restrict__ W5,
    float* __restrict__ wt)
{
    int b = blockIdx.x;
    if (b < CNT_BLKS) {
        int base = (b * 256 + threadIdx.x) * 4;
        if (base >= N_EDGES) return;
        int4 d = *reinterpret_cast<const int4*>(ei + N_EDGES + base);
        int r0 = atomicAdd(&g_deg[d.x], 1);
        int r1 = atomicAdd(&g_deg[d.y], 1);
        int r2 = atomicAdd(&g_deg[d.z], 1);
        int r3 = atomicAdd(&g_deg[d.w], 1);
        *reinterpret_cast<int4*>(g_rank + base) = make_int4(r0, r1, r2, r3);
    } else {
        int idx = (b - CNT_BLKS) * 256 + threadIdx.x;
        const int S0 = 256 * INC;
        const int S = 256 * HIDC;
        const float* W; int K; int loc; float* out;
        if (idx < S0) { W = W0; K = INC; loc = idx; out = wt; }
        else {
            int r = idx - S0;
            int slot = r / S; loc = r - slot * S; K = HIDC;
            if (slot >= 5) return;
            const float* Ws[5] = { W1, W2, W3, W4, W5 };
            W = Ws[slot]; out = wt + (slot + 1) * HIDC * HIDC;
        }
        int n = loc / K, k = loc - n * K;
        out[(size_t)n * K + k] = tf32r(__ldg(W + (size_t)k * 256 + n));
    }
}

// Scan also re-zeros g_deg (keeps the zero-at-entry invariant; no memset node).
__global__ void __launch_bounds__(1024) scan_kernel() {
    __shared__ int part[1024];
    const int t = threadIdx.x;
    const int CH = 10;
    int local[CH];
    int base = t * CH, s = 0;
    #pragma unroll
    for (int k = 0; k < CH; k++) {
        int idx = base + k;
        local[k] = (idx < N_NODES) ? g_deg[idx] : 0;
        if (idx < N_NODES) g_deg[idx] = 0;
        s += local[k];
    }
    part[t] = s;
    __syncthreads();
    for (int d = 1; d < 1024; d <<= 1) {
        int v = (t >= d) ? part[t - d] : 0;
        __syncthreads();
        part[t] += v;
        __syncthreads();
    }
    int run = (t > 0) ? part[t - 1] : 0;
    #pragma unroll
    for (int k = 0; k < CH; k++) {
        int idx = base + k;
        if (idx < N_NODES) { g_off[idx] = run; run += local[k]; }
    }
    if (t == 1023) g_off[N_NODES] = part[1023];
}

__global__ void __launch_bounds__(256) fill_kernel(const int* __restrict__ ei) {
    int base = (blockIdx.x * blockDim.x + threadIdx.x) * 4;
    if (base >= N_EDGES) return;
    int4 s = *reinterpret_cast<const int4*>(ei + base);
    int4 d = *reinterpret_cast<const int4*>(ei + N_EDGES + base);
    int4 r = *reinterpret_cast<const int4*>(g_rank + base);
    g_eid[__ldg(g_off + d.x) + r.x] = s.x;
    g_eid[__ldg(g_off + d.y) + r.y] = s.y;
    g_eid[__ldg(g_off + d.z) + r.z] = s.z;
    g_eid[__ldg(g_off + d.w) + r.w] = s.w;
}

// ---------------------------------------------------------------------------
// gather via cp.async: warp per node, 4-edge batches double-buffered in
// per-warp private smem. Each lane copies & reads back its own 16B slices,
// so only cp.async.wait_group ordering is needed (no warp sync).
// C4 = 32 (C=128, row 512B) or 64 (C=256, row 1024B).
// ---------------------------------------------------------------------------
template <int C4>
__global__ void __launch_bounds__(256) gather_cp(
    const float* __restrict__ feat, float* __restrict__ agg)
{
    extern __shared__ __align__(16) char gsm[];
    const int ROWB = C4 * 16;                    // bytes per feature row
    const int wslot = threadIdx.x >> 5;
    const int lane  = threadIdx.x & 31;
    char* wptr = gsm + wslot * (8 * ROWB);       // 2 stages x 4 rows
    const uint32_t wbase = smem_u32(wptr);

    int w = blockIdx.x * 8 + wslot;
    if (w >= N_NODES) return;
    int beg = __ldg(g_off + w), end = __ldg(g_off + w + 1);
    const float4* f = reinterpret_cast<const float4*>(feat);

    float4 a0 = __ldg(f + (size_t)w * C4 + lane);
    float4 a1 = make_float4(0.f, 0.f, 0.f, 0.f);
    if (C4 == 64) a1 = __ldg(f + (size_t)w * C4 + lane + 32);

    const int nb = (end - beg) >> 2;

    auto prefetch = [&](int stage, int j) {
        #pragma unroll
        for (int e = 0; e < 4; e++) {
            int s = __ldg(g_eid + j + e);
            const char* src = reinterpret_cast<const char*>(feat)
                              + (size_t)s * ROWB + lane * 16;
            uint32_t dst = wbase + stage * (4 * ROWB) + e * ROWB + lane * 16;
            cp16(dst, src, 16);
            if (C4 == 64) cp16(dst + 512, src + 512, 16);
        }
        cp_commit();
    };

    if (nb > 0) prefetch(0, beg);
    if (nb > 1) prefetch(1, beg + 4);

    for (int b = 0; b < nb; b++) {
        if (b + 1 < nb) cp_wait<1>(); else cp_wait<0>();
        const char* st = wptr + (b & 1) * (4 * ROWB);
        #pragma unroll
        for (int e = 0; e < 4; e++) {
            float4 v = *reinterpret_cast<const float4*>(st + e * ROWB + lane * 16);
            a0.x += v.x; a0.y += v.y; a0.z += v.z; a0.w += v.w;
            if (C4 == 64) {
                float4 v2 = *reinterpret_cast<const float4*>(st + e * ROWB + 512 + lane * 16);
                a1.x += v2.x; a1.y += v2.y; a1.z += v2.z; a1.w += v2.w;
            }
        }
        if (b + 2 < nb) prefetch(b & 1, beg + (b + 2) * 4);
    }

    // scalar tail (deg % 4 edges)
    for (int j = beg + nb * 4; j < end; j++) {
        int s = __ldg(g_eid + j);
        float4 v = __ldg(f + (size_t)s * C4 + lane);
        a0.x += v.x; a0.y += v.y; a0.z += v.z; a0.w += v.w;
        if (C4 == 64) {
            float4 v2 = __ldg(f + (size_t)s * C4 + lane + 32);
            a1.x += v2.x; a1.y += v2.y; a1.z += v2.z; a1.w += v2.w;
        }
    }

    a0.x = tf32r(a0.x); a0.y = tf32r(a0.y); a0.z = tf32r(a0.z); a0.w = tf32r(a0.w);
    reinterpret_cast<float4*>(agg)[(size_t)w * C4 + lane] = a0;
    if (C4 == 64) {
        a1.x = tf32r(a1.x); a1.y = tf32r(a1.y); a1.z = tf32r(a1.z); a1.w = tf32r(a1.w);
        reinterpret_cast<float4*>(agg)[(size_t)w * C4 + lane + 32] = a1;
    }
}

#define GATHER_SMEM(C4) (8 * 8 * (C4) * 16)   // 8 warps x 2 stages x 4 rows

// ---------------------------------------------------------------------------
// GEMM (frozen R13): C[M,256] = A[M,K] @ Wt^T (+bias, opt ReLU, opt round).
// Operands pre-rounded; ldmatrix.x4 fragment loads (conflict-free, LDT=20).
// CTA 64x128xK16, 8 warps (2M x 4N), 3-stage cp.async, 1 barrier/iter.
// ---------------------------------------------------------------------------
#define BM 64
#define BN 128
#define LDT 20
#define STAGE_F ((BM + BN) * LDT)
#define STAGE_B (STAGE_F * 4)
#define ATB (BM * LDT * 4)

__global__ void __launch_bounds__(256) gemm_mma(
    const float* __restrict__ A, const float* __restrict__ Bt,
    const float* __restrict__ bias, float* __restrict__ C,
    int M, int K, int relu, int rnd)
{
    __shared__ __align__(16) float sm[3 * STAGE_F];   // 46080 B
    const uint32_t sbase = smem_u32(sm);

    const int tid = threadIdx.x;
    const int lane = tid & 31, wid = tid >> 5;
    const int warp_m = wid & 1, warp_n = wid >> 1;
    const int g = lane >> 2, tig = lane & 3;
    const int nb = blockIdx.x * BN;
    const int mb = blockIdx.y * BM;

    const int lr  = tid >> 2;
    const int lc4 = tid & 3;

    const int q  = lane >> 3;
    const int rr = lane & 7;
    uint32_t offA[2][2], offB[2][2];
    #pragma unroll
    for (int mt = 0; mt < 2; mt++)
        #pragma unroll
        for (int k8 = 0; k8 < 2; k8++)
            offA[mt][k8] = ((warp_m * 32 + mt * 16 + (q & 1) * 8 + rr) * LDT
                            + k8 * 8 + (q >> 1) * 4) * 4;
    #pragma unroll
    for (int np = 0; np < 2; np++)
        #pragma unroll
        for (int k8 = 0; k8 < 2; k8++)
            offB[np][k8] = ATB + ((warp_n * 32 + np * 16 + (q >> 1) * 8 + rr) * LDT
                                  + k8 * 8 + (q & 1) * 4) * 4;

    float acc[2][4][4];
    #pragma unroll
    for (int mt = 0; mt < 2; mt++)
        #pragma unroll
        for (int nt = 0; nt < 4; nt++)
            #pragma unroll
            for (int qq = 0; qq < 4; qq++) acc[mt][nt][qq] = 0.f;

    const int NC = K >> 4;

    auto issue = [&](int buf, int k0) {
        const uint32_t stg = sbase + buf * STAGE_B;
        {
            int grow = mb + lr;
            int rowc = grow < M ? grow : M - 1;
            const float* gp = A + (size_t)rowc * K + k0 + lc4 * 4;
            cp16(stg + (lr * LDT + lc4 * 4) * 4, gp, grow < M ? 16 : 0);
        }
        #pragma unroll
        for (int t = 0; t < 2; t++) {
            int r = lr + t * 64;
            const float* gp = Bt + (size_t)(nb + r) * K + k0 + lc4 * 4;
            cp16(stg + ATB + (r * LDT + lc4 * 4) * 4, gp, 16);
        }
        cp_commit();
    };

    issue(0, 0);
    if (NC > 1) issue(1, 16);

    for (int i = 0; i < NC; i++) {
        if (i + 1 < NC) cp_wait<1>(); else cp_wait<0>();
        __syncthreads();
        if (i + 2 < NC) issue((i + 2) % 3, (i + 2) << 4);

        const uint32_t stg = sbase + (i % 3) * STAGE_B;

        #pragma unroll
        for (int k8 = 0; k8 < 2; k8++) {
            uint32_t af[2][4], bf[2][4];
            ldsm_x4(af[0][0], af[0][1], af[0][2], af[0][3], stg + offA[0][k8]);
            ldsm_x4(af[1][0], af[1][1], af[1][2], af[1][3], stg + offA[1][k8]);
            ldsm_x4(bf[0][0], bf[0][1], bf[0][2], bf[0][3], stg + offB[0][k8]);
            ldsm_x4(bf[1][0], bf[1][1], bf[1][2], bf[1][3], stg + offB[1][k8]);
            #pragma unroll
            for (int nt = 0; nt < 4; nt++) {
                uint32_t b0 = bf[nt >> 1][(nt & 1) * 2];
                uint32_t b1 = bf[nt >> 1][(nt & 1) * 2 + 1];
                #pragma unroll
                for (int mt = 0; mt < 2; mt++)
                    mma_tf32(acc[mt][nt], af[mt][0], af[mt][1], af[mt][2], af[mt][3], b0, b1);
            }
        }
    }

    #pragma unroll
    for (int nt = 0; nt < 4; nt++) {
        int col = nb + warp_n * 32 + nt * 8 + 2 * tig;
        float2 bv = __ldg(reinterpret_cast<const float2*>(bias + col));
        #pragma unroll
        for (int mt = 0; mt < 2; mt++) {
            int row0 = mb + warp_m * 32 + mt * 16 + g;
            float2 o0 = make_float2(acc[mt][nt][0] + bv.x, acc[mt][nt][1] + bv.y);
            float2 o1 = make_float2(acc[mt][nt][2] + bv.x, acc[mt][nt][3] + bv.y);
            if (relu) {
                o0.x = fmaxf(o0.x, 0.f); o0.y = fmaxf(o0.y, 0.f);
                o1.x = fmaxf(o1.x, 0.f); o1.y = fmaxf(o1.y, 0.f);
            }
            if (rnd) {
                o0.x = tf32r(o0.x); o0.y = tf32r(o0.y);
                o1.x = tf32r(o1.x); o1.y = tf32r(o1.y);
            }
            if (row0 < M)
                *reinterpret_cast<float2*>(C + (size_t)row0 * 256 + col) = o0;
            if (row0 + 8 < M)
                *reinterpret_cast<float2*>(C + (size_t)(row0 + 8) * 256 + col) = o1;
        }
    }
}

// ---------------------------------------------------------------------------
static void launch_layer(const float* feat, int C,
                         const float* Wta, const float* ba,
                         const float* Wtb, const float* bb,
                         float* agg, float* hid, float* out,
                         int out_relu, int out_rnd)
{
    int gblocks = (N_NODES + 7) / 8;
    if (C == INC)
        gather_cp<32><<<gblocks, 256, GATHER_SMEM(32)>>>(feat, agg);
    else
        gather_cp<64><<<gblocks, 256, GATHER_SMEM(64)>>>(feat, agg);
    dim3 grid(256 / BN, (N_NODES + BM - 1) / BM);
    gemm_mma<<<grid, 256>>>(agg, Wta, ba, hid, N_NODES, C, 1, 1);
    gemm_mma<<<grid, 256>>>(hid, Wtb, bb, out, N_NODES, HIDC, out_relu, out_rnd);
}

extern "C" void kernel_launch(void* const* d_in, const int* in_sizes, int n_in,
                              void* d_out, int out_size)
{
    const float* x  = (const float*)d_in[0];
    const int*   ei = (const int*)  d_in[1];

    // 64KB dynamic smem for the C=256 gather (exceeds 48KB default).
    cudaFuncSetAttribute(gather_cp<64>, cudaFuncAttributeMaxDynamicSharedMemorySize,
                         GATHER_SMEM(64));

    float *agg, *hid, *f1, *f2, *wt;
    cudaGetSymbolAddress((void**)&agg, g_agg);
    cudaGetSymbolAddress((void**)&hid, g_hid);
    cudaGetSymbolAddress((void**)&f1,  g_f1);
    cudaGetSymbolAddress((void**)&f2,  g_f2);
    cudaGetSymbolAddress((void**)&wt,  g_wt);

    // CSR build. g_deg is zero at entry (static init + scan re-zeroing).
    count_and_transpose<<<CNT_BLKS + TW_BLKS, 256>>>(
        ei,
        (const float*)d_in[2], (const float*)d_in[4], (const float*)d_in[6],
        (const float*)d_in[8], (const float*)d_in[10], (const float*)d_in[12], wt);
    scan_kernel<<<1, 1024>>>();
    fill_kernel<<<(N_EDGES / 4 + 255) / 256, 256>>>(ei);

    float* Wt[6];
    for (int i = 0; i < 6; i++) Wt[i] = wt + i * HIDC * HIDC;
    const float* bv[6] = { (const float*)d_in[3],  (const float*)d_in[5],
                           (const float*)d_in[7],  (const float*)d_in[9],
                           (const float*)d_in[11], (const float*)d_in[13] };

    launch_layer(x,  INC,  Wt[0], bv[0], Wt[1], bv[1], agg, hid, f1, 1, 1);
    launch_layer(f1, HIDC, Wt[2], bv[2], Wt[3], bv[3], agg, hid, f2, 1, 1);
    launch_layer(f2, HIDC, Wt[4], bv[4], Wt[5], bv[5], agg, hid, (float*)d_out, 0, 0);
}

// round 17
// speedup vs baseline: 1.0375x; 1.0375x over previous
#include <cuda_runtime.h>
#include <cstdint>
#include <cstddef>

// ---------------------------------------------------------------------------
// GIN (3-layer) — Round 17.
// = R15 (233.5us; gather/GEMM/CSR all frozen at converged forms)
// + PDL: all kernels griddepcontrol.wait at entry, launched with
//   programmaticStreamSerializationAllowed=1 to hide launch latency.
// ---------------------------------------------------------------------------

#define N_NODES 10000
#define N_EDGES 640000
#define INC     128
#define HIDC    256

__device__ float g_agg[N_NODES * HIDC];
__device__ float g_hid[N_NODES * HIDC];
__device__ float g_f1 [N_NODES * HIDC];
__device__ float g_f2 [N_NODES * HIDC];
__device__ float g_wt [6 * HIDC * HIDC];
__device__ int   g_deg[N_NODES];        // invariant: zero at kernel_launch entry
__device__ int   g_off[N_NODES + 1];
__device__ int   g_rank[N_EDGES];
__device__ int   g_eid[N_EDGES];

// ---------------------------------------------------------------------------
__device__ __forceinline__ void pdl_wait() {
    asm volatile("griddepcontrol.wait;" ::: "memory");
}
__device__ __forceinline__ uint32_t smem_u32(const void* p) {
    uint32_t a;
    asm("{ .reg .u64 t; cvta.to.shared.u64 t, %1; cvt.u32.u64 %0, t; }" : "=r"(a) : "l"(p));
    return a;
}
__device__ __forceinline__ float tf32r(float v) {
    uint32_t r;
    asm("cvt.rna.tf32.f32 %0, %1;" : "=r"(r) : "f"(v));
    return __uint_as_float(r);
}
__device__ __forceinline__ void cp16(uint32_t saddr, const void* g, int sz) {
    asm volatile("cp.async.cg.shared.global [%0], [%1], 16, %2;"
                 :: "r"(saddr), "l"(g), "r"(sz) : "memory");
}
__device__ __forceinline__ void cp_commit() {
    asm volatile("cp.async.commit_group;" ::: "memory");
}
template <int N>
__device__ __forceinline__ void cp_wait() {
    asm volatile("cp.async.wait_group %0;" :: "n"(N) : "memory");
}
__device__ __forceinline__ void ldsm_x4(uint32_t& r0, uint32_t& r1,
                                        uint32_t& r2, uint32_t& r3,
                                        uint32_t addr) {
    asm volatile("ldmatrix.sync.aligned.m8n8.x4.shared.b16 {%0,%1,%2,%3}, [%4];"
                 : "=r"(r0), "=r"(r1), "=r"(r2), "=r"(r3) : "r"(addr));
}
__device__ __forceinline__ void mma_tf32(float* c, uint32_t a0, uint32_t a1,
                                         uint32_t a2, uint32_t a3,
                                         uint32_t b0, uint32_t b1) {
    asm volatile(
        "mma.sync.aligned.m16n8k8.row.col.f32.tf32.tf32.f32 "
        "{%0,%1,%2,%3}, {%4,%5,%6,%7}, {%8,%9}, {%0,%1,%2,%3};"
        : "+f"(c[0]), "+f"(c[1]), "+f"(c[2]), "+f"(c[3])
        : "r"(a0), "r"(a1), "r"(a2), "r"(a3), "r"(b0), "r"(b1));
}

// ---------------------------------------------------------------------------
// Fused: blocks [0, CNT_BLKS) degree count + per-edge rank; rest: transpose.
// ---------------------------------------------------------------------------
#define CNT_BLKS 625
#define TW_ELEMS (256 * INC + 5 * 256 * HIDC)
#define TW_BLKS  ((TW_ELEMS + 255) / 256)

__global__ void __launch_bounds__(256) count_and_transpose(
    const int* __restrict__ ei,
    const float* __restrict__ W0, const float* __restrict__ W1,
    const float* __restrict__ W2, const float* __restrict__ W3,
    const float* __restrict__ W4, const float* __restrict__ W5,
    float* __restrict__ wt)
{
    pdl_wait();
    int b = blockIdx.x;
    if (b < CNT_BLKS) {
        int base = (b * 256 + threadIdx.x) * 4;
        if (base >= N_EDGES) return;
        int4 d = *reinterpret_cast<const int4*>(ei + N_EDGES + base);
        int r0 = atomicAdd(&g_deg[d.x], 1);
        int r1 = atomicAdd(&g_deg[d.y], 1);
        int r2 = atomicAdd(&g_deg[d.z], 1);
        int r3 = atomicAdd(&g_deg[d.w], 1);
        *reinterpret_cast<int4*>(g_rank + base) = make_int4(r0, r1, r2, r3);
    } else {
        int idx = (b - CNT_BLKS) * 256 + threadIdx.x;
        const int S0 = 256 * INC;
        const int S = 256 * HIDC;
        const float* W; int K; int loc; float* out;
        if (idx < S0) { W = W0; K = INC; loc = idx; out = wt; }
        else {
            int r = idx - S0;
            int slot = r / S; loc = r - slot * S; K = HIDC;
            if (slot >= 5) return;
            const float* Ws[5] = { W1, W2, W3, W4, W5 };
            W = Ws[slot]; out = wt + (slot + 1) * HIDC * HIDC;
        }
        int n = loc / K, k = loc - n * K;
        out[(size_t)n * K + k] = tf32r(__ldg(W + (size_t)k * 256 + n));
    }
}

// Scan also re-zeros g_deg (keeps the zero-at-entry invariant; no memset node).
__global__ void __launch_bounds__(1024) scan_kernel() {
    pdl_wait();
    __shared__ int part[1024];
    const int t = threadIdx.x;
    const int CH = 10;
    int local[CH];
    int base = t * CH, s = 0;
    #pragma unroll
    for (int k = 0; k < CH; k++) {
        int idx = base + k;
        local[k] = (idx < N_NODES) ? g_deg[idx] : 0;
        if (idx < N_NODES) g_deg[idx] = 0;
        s += local[k];
    }
    part[t] = s;
    __syncthreads();
    for (int d = 1; d < 1024; d <<= 1) {
        int v = (t >= d) ? part[t - d] : 0;
        __syncthreads();
        part[t] += v;
        __syncthreads();
    }
    int run = (t > 0) ? part[t - 1] : 0;
    #pragma unroll
    for (int k = 0; k < CH; k++) {
        int idx = base + k;
        if (idx < N_NODES) { g_off[idx] = run; run += local[k]; }
    }
    if (t == 1023) g_off[N_NODES] = part[1023];
}

__global__ void __launch_bounds__(256) fill_kernel(const int* __restrict__ ei) {
    pdl_wait();
    int base = (blockIdx.x * blockDim.x + threadIdx.x) * 4;
    if (base >= N_EDGES) return;
    int4 s = *reinterpret_cast<const int4*>(ei + base);
    int4 d = *reinterpret_cast<const int4*>(ei + N_EDGES + base);
    int4 r = *reinterpret_cast<const int4*>(g_rank + base);
    g_eid[__ldg(g_off + d.x) + r.x] = s.x;
    g_eid[__ldg(g_off + d.y) + r.y] = s.y;
    g_eid[__ldg(g_off + d.z) + r.z] = s.z;
    g_eid[__ldg(g_off + d.w) + r.w] = s.w;
}

// ---------------------------------------------------------------------------
// gather (frozen R5 form + tf32-rounded store): warp per node, 4 edges in
// flight.
// ---------------------------------------------------------------------------
__global__ void __launch_bounds__(256) gather_kernel(
    const float* __restrict__ feat, float* __restrict__ agg, int C4)
{
    pdl_wait();
    int w = (blockIdx.x * blockDim.x + threadIdx.x) >> 5;
    if (w >= N_NODES) return;
    int lane = threadIdx.x & 31;
    int beg = __ldg(g_off + w), end = __ldg(g_off + w + 1);
    const float4* f = reinterpret_cast<const float4*>(feat);

    if (C4 == 32) {
        float4 a = __ldg(f + (size_t)w * 32 + lane);
        int j = beg;
        for (; j + 3 < end; j += 4) {
            int s0 = __ldg(g_eid + j),     s1 = __ldg(g_eid + j + 1);
            int s2 = __ldg(g_eid + j + 2), s3 = __ldg(g_eid + j + 3);
            float4 v0 = __ldg(f + (size_t)s0 * 32 + lane);
            float4 v1 = __ldg(f + (size_t)s1 * 32 + lane);
            float4 v2 = __ldg(f + (size_t)s2 * 32 + lane);
            float4 v3 = __ldg(f + (size_t)s3 * 32 + lane);
            a.x += (v0.x + v1.x) + (v2.x + v3.x);
            a.y += (v0.y + v1.y) + (v2.y + v3.y);
            a.z += (v0.z + v1.z) + (v2.z + v3.z);
            a.w += (v0.w + v1.w) + (v2.w + v3.w);
        }
        for (; j < end; j++) {
            int s0 = __ldg(g_eid + j);
            float4 v0 = __ldg(f + (size_t)s0 * 32 + lane);
            a.x += v0.x; a.y += v0.y; a.z += v0.z; a.w += v0.w;
        }
        a.x = tf32r(a.x); a.y = tf32r(a.y); a.z = tf32r(a.z); a.w = tf32r(a.w);
        reinterpret_cast<float4*>(agg)[(size_t)w * 32 + lane] = a;
    } else {
        float4 a0 = __ldg(f + (size_t)w * 64 + lane);
        float4 a1 = __ldg(f + (size_t)w * 64 + lane + 32);
        int j = beg;
        for (; j + 3 < end; j += 4) {
            int s0 = __ldg(g_eid + j),     s1 = __ldg(g_eid + j + 1);
            int s2 = __ldg(g_eid + j + 2), s3 = __ldg(g_eid + j + 3);
            const float4* p0 = f + (size_t)s0 * 64;
            const float4* p1 = f + (size_t)s1 * 64;
            const float4* p2 = f + (size_t)s2 * 64;
            const float4* p3 = f + (size_t)s3 * 64;
            float4 u0 = __ldg(p0 + lane), w0 = __ldg(p0 + lane + 32);
            float4 u1 = __ldg(p1 + lane), w1 = __ldg(p1 + lane + 32);
            float4 u2 = __ldg(p2 + lane), w2 = __ldg(p2 + lane + 32);
            float4 u3 = __ldg(p3 + lane), w3 = __ldg(p3 + lane + 32);
            a0.x += (u0.x + u1.x) + (u2.x + u3.x);
            a0.y += (u0.y + u1.y) + (u2.y + u3.y);
            a0.z += (u0.z + u1.z) + (u2.z + u3.z);
            a0.w += (u0.w + u1.w) + (u2.w + u3.w);
            a1.x += (w0.x + w1.x) + (w2.x + w3.x);
            a1.y += (w0.y + w1.y) + (w2.y + w3.y);
            a1.z += (w0.z + w1.z) + (w2.z + w3.z);
            a1.w += (w0.w + w1.w) + (w2.w + w3.w);
        }
        for (; j < end; j++) {
            int s0 = __ldg(g_eid + j);
            const float4* p0 = f + (size_t)s0 * 64;
            float4 u0 = __ldg(p0 + lane), w0 = __ldg(p0 + lane + 32);
            a0.x += u0.x; a0.y += u0.y; a0.z += u0.z; a0.w += u0.w;
            a1.x += w0.x; a1.y += w0.y; a1.z += w0.z; a1.w += w0.w;
        }
        a0.x = tf32r(a0.x); a0.y = tf32r(a0.y); a0.z = tf32r(a0.z); a0.w = tf32r(a0.w);
        a1.x = tf32r(a1.x); a1.y = tf32r(a1.y); a1.z = tf32r(a1.z); a1.w = tf32r(a1.w);
        reinterpret_cast<float4*>(agg)[(size_t)w * 64 + lane] = a0;
        reinterpret_cast<float4*>(agg)[(size_t)w * 64 + lane + 32] = a1;
    }
}

// ---------------------------------------------------------------------------
// GEMM (frozen R13): C[M,256] = A[M,K] @ Wt^T (+bias, opt ReLU, opt round).
// Operands pre-rounded; ldmatrix.x4 fragment loads (conflict-free, LDT=20).
// CTA 64x128xK16, 8 warps (2M x 4N), 3-stage cp.async, 1 barrier/iter.
// ---------------------------------------------------------------------------
#define BM 64
#define BN 128
#define LDT 20
#define STAGE_F ((BM + BN) * LDT)
#define STAGE_B (STAGE_F * 4)
#define ATB (BM * LDT * 4)

__global__ void __launch_bounds__(256) gemm_mma(
    const float* __restrict__ A, const float* __restrict__ Bt,
    const float* __restrict__ bias, float* __restrict__ C,
    int M, int K, int relu, int rnd)
{
    __shared__ __align__(16) float sm[3 * STAGE_F];   // 46080 B
    const uint32_t sbase = smem_u32(sm);

    const int tid = threadIdx.x;
    const int lane = tid & 31, wid = tid >> 5;
    const int warp_m = wid & 1, warp_n = wid >> 1;
    const int g = lane >> 2, tig = lane & 3;
    const int nb = blockIdx.x * BN;
    const int mb = blockIdx.y * BM;

    const int lr  = tid >> 2;
    const int lc4 = tid & 3;

    const int q  = lane >> 3;
    const int rr = lane & 7;
    uint32_t offA[2][2], offB[2][2];
    #pragma unroll
    for (int mt = 0; mt < 2; mt++)
        #pragma unroll
        for (int k8 = 0; k8 < 2; k8++)
            offA[mt][k8] = ((warp_m * 32 + mt * 16 + (q & 1) * 8 + rr) * LDT
                            + k8 * 8 + (q >> 1) * 4) * 4;
    #pragma unroll
    for (int np = 0; np < 2; np++)
        #pragma unroll
        for (int k8 = 0; k8 < 2; k8++)
            offB[np][k8] = ATB + ((warp_n * 32 + np * 16 + (q >> 1) * 8 + rr) * LDT
                                  + k8 * 8 + (q & 1) * 4) * 4;

    float acc[2][4][4];
    #pragma unroll
    for (int mt = 0; mt < 2; mt++)
        #pragma unroll
        for (int nt = 0; nt < 4; nt++)
            #pragma unroll
            for (int qq = 0; qq < 4; qq++) acc[mt][nt][qq] = 0.f;

    const int NC = K >> 4;

    auto issue = [&](int buf, int k0) {
        const uint32_t stg = sbase + buf * STAGE_B;
        {
            int grow = mb + lr;
            int rowc = grow < M ? grow : M - 1;
            const float* gp = A + (size_t)rowc * K + k0 + lc4 * 4;
            cp16(stg + (lr * LDT + lc4 * 4) * 4, gp, grow < M ? 16 : 0);
        }
        #pragma unroll
        for (int t = 0; t < 2; t++) {
            int r = lr + t * 64;
            const float* gp = Bt + (size_t)(nb + r) * K + k0 + lc4 * 4;
            cp16(stg + ATB + (r * LDT + lc4 * 4) * 4, gp, 16);
        }
        cp_commit();
    };

    // Wait for upstream grid's writes before first dependent read.
    pdl_wait();

    issue(0, 0);
    if (NC > 1) issue(1, 16);

    for (int i = 0; i < NC; i++) {
        if (i + 1 < NC) cp_wait<1>(); else cp_wait<0>();
        __syncthreads();
        if (i + 2 < NC) issue((i + 2) % 3, (i + 2) << 4);

        const uint32_t stg = sbase + (i % 3) * STAGE_B;

        #pragma unroll
        for (int k8 = 0; k8 < 2; k8++) {
            uint32_t af[2][4], bf[2][4];
            ldsm_x4(af[0][0], af[0][1], af[0][2], af[0][3], stg + offA[0][k8]);
            ldsm_x4(af[1][0], af[1][1], af[1][2], af[1][3], stg + offA[1][k8]);
            ldsm_x4(bf[0][0], bf[0][1], bf[0][2], bf[0][3], stg + offB[0][k8]);
            ldsm_x4(bf[1][0], bf[1][1], bf[1][2], bf[1][3], stg + offB[1][k8]);
            #pragma unroll
            for (int nt = 0; nt < 4; nt++) {
                uint32_t b0 = bf[nt >> 1][(nt & 1) * 2];
                uint32_t b1 = bf[nt >> 1][(nt & 1) * 2 + 1];
                #pragma unroll
                for (int mt = 0; mt < 2; mt++)
                    mma_tf32(acc[mt][nt], af[mt][0], af[mt][1], af[mt][2], af[mt][3], b0, b1);
            }
        }
    }

    #pragma unroll
    for (int nt = 0; nt < 4; nt++) {
        int col = nb + warp_n * 32 + nt * 8 + 2 * tig;
        float2 bv = __ldg(reinterpret_cast<const float2*>(bias + col));
        #pragma unroll
        for (int mt = 0; mt < 2; mt++) {
            int row0 = mb + warp_m * 32 + mt * 16 + g;
            float2 o0 = make_float2(acc[mt][nt][0] + bv.x, acc[mt][nt][1] + bv.y);
            float2 o1 = make_float2(acc[mt][nt][2] + bv.x, acc[mt][nt][3] + bv.y);
            if (relu) {
                o0.x = fmaxf(o0.x, 0.f); o0.y = fmaxf(o0.y, 0.f);
                o1.x = fmaxf(o1.x, 0.f); o1.y = fmaxf(o1.y, 0.f);
            }
            if (rnd) {
                o0.x = tf32r(o0.x); o0.y = tf32r(o0.y);
                o1.x = tf32r(o1.x); o1.y = tf32r(o1.y);
            }
            if (row0 < M)
                *reinterpret_cast<float2*>(C + (size_t)row0 * 256 + col) = o0;
            if (row0 + 8 < M)
                *reinterpret_cast<float2*>(C + (size_t)(row0 + 8) * 256 + col) = o1;
        }
    }
}

// ---------------------------------------------------------------------------
// PDL launch helper: programmatic stream serialization lets each dependent
// kernel be scheduled while its predecessor drains (wait gates the data).
// ---------------------------------------------------------------------------
template <typename F, typename... Args>
static void launch_pdl(F kernel, dim3 grid, dim3 block, Args... args)
{
    cudaLaunchConfig_t cfg = {};
    cfg.gridDim = grid;
    cfg.blockDim = block;
    cfg.dynamicSmemBytes = 0;
    cudaLaunchAttribute attr[1];
    attr[0].id = cudaLaunchAttributeProgrammaticStreamSerialization;
    attr[0].val.programmaticStreamSerializationAllowed = 1;
    cfg.attrs = attr;
    cfg.numAttrs = 1;
    cudaLaunchKernelEx(&cfg, kernel, args...);
}

static void launch_layer(const float* feat, int C,
                         const float* Wta, const float* ba,
                         const float* Wtb, const float* bb,
                         float* agg, float* hid, float* out,
                         int out_relu, int out_rnd)
{
    launch_pdl(gather_kernel, dim3((N_NODES * 32 + 255) / 256), dim3(256),
               feat, agg, C / 4);
    dim3 grid(256 / BN, (N_NODES + BM - 1) / BM);
    launch_pdl(gemm_mma, grid, dim3(256), agg, Wta, ba, hid, N_NODES, C, 1, 1);
    launch_pdl(gemm_mma, grid, dim3(256), hid, Wtb, bb, out, N_NODES, HIDC,
               out_relu, out_rnd);
}

extern "C" void kernel_launch(void* const* d_in, const int* in_sizes, int n_in,
                              void* d_out, int out_size)
{
    const float* x  = (const float*)d_in[0];
    const int*   ei = (const int*)  d_in[1];

    float *agg, *hid, *f1, *f2, *wt;
    cudaGetSymbolAddress((void**)&agg, g_agg);
    cudaGetSymbolAddress((void**)&hid, g_hid);
    cudaGetSymbolAddress((void**)&f1,  g_f1);
    cudaGetSymbolAddress((void**)&f2,  g_f2);
    cudaGetSymbolAddress((void**)&wt,  g_wt);

    // CSR build. g_deg is zero at entry (static init + scan re-zeroing).
    launch_pdl(count_and_transpose, dim3(CNT_BLKS + TW_BLKS), dim3(256),
               ei,
               (const float*)d_in[2], (const float*)d_in[4], (const float*)d_in[6],
               (const float*)d_in[8], (const float*)d_in[10], (const float*)d_in[12],
               wt);
    launch_pdl(scan_kernel, dim3(1), dim3(1024));
    launch_pdl(fill_kernel, dim3((N_EDGES / 4 + 255) / 256), dim3(256), ei);

    float* Wt[6];
    for (int i = 0; i < 6; i++) Wt[i] = wt + i * HIDC * HIDC;
    const float* bv[6] = { (const float*)d_in[3],  (const float*)d_in[5],
                           (const float*)d_in[7],  (const float*)d_in[9],
                           (const float*)d_in[11], (const float*)d_in[13] };

    launch_layer(x,  INC,  Wt[0], bv[0], Wt[1], bv[1], agg, hid, f1, 1, 1);
    launch_layer(f1, HIDC, Wt[2], bv[2], Wt[3], bv[3], agg, hid, f2, 1, 1);
    launch_layer(f2, HIDC, Wt[4], bv[4], Wt[5], bv[5], agg, hid, (float*)d_out, 0, 0);
}